// round 14
// baseline (speedup 1.0000x reference)
#include <cuda_runtime.h>
#include <cuda_fp16.h>
#include <cstdint>

// ---------------- problem constants ----------------
#define N_PIX   65536
#define CDIM    64
#define KCODES  512
#define HWSZ    4096
#define CHW     (CDIM * HWSZ)

#define OUT_Q_ELEMS  (N_PIX * CDIM)
#define OUT_LOSS_OFF OUT_Q_ELEMS
#define OUT_PERP_OFF (OUT_Q_ELEMS + 1)
#define OUT_ACT_OFF  (OUT_Q_ELEMS + 2)
#define OUT_IDX_OFF  (OUT_Q_ELEMS + 3)

#define TILE_P   128
#define NBLK     (N_PIX / TILE_P)      // 512
#define CODES_PER_CHUNK 128
#define NCHUNK   (KCODES / CODES_PER_CHUNK)   // 4

// eps_p = EPS_C * ||x_p|| * max||e|| + EPS_M   (rigorous 1-term fp16 bound)
#define EPS_C 4.1e-3f
#define EPS_M 0.07f

// ---------------- device scratch ----------------
__device__ __align__(16) uint16_t g_Bh[KCODES * CDIM];   // fp16 codebook
__device__ __align__(16) float    g_en2[KCODES];
__device__ int   g_emax_i = 0;                            // max en2 as int bits
__device__ int   g_hist[KCODES];
__device__ float g_part[NBLK];

// ---------------- smem layout ----------------
#define OFF_A     0          // 16384: fp16(-2x), 128 rows x 128B swizzled
#define OFF_B     16384      // 2 x 16384 double buffer (128 codes x 128B)
#define OFF_EN2   49152      // 2048
#define OFF_TOPV  51200      // 2048: 128 x 4 floats (pair minima, idx packed)
#define OFF_HIST  53248      // 2048
#define OFF_XN2   55296      // 1024: 2 halves x 128 partial ||x||^2
#define OFF_WIN   56320      // 512
#define OFF_WS    56832      // 32
#define SMEM_MAIN 56864

// ---------------- PTX helpers (compute_103-legal only) ----------------
__device__ __forceinline__ uint32_t s2u(const void* p) {
    uint32_t a;
    asm("{ .reg .u64 t; cvta.to.shared.u64 t, %1; cvt.u32.u64 %0, t; }"
        : "=r"(a) : "l"(p));
    return a;
}
__device__ __forceinline__ void ldsm_x4(uint32_t& r0, uint32_t& r1,
                                        uint32_t& r2, uint32_t& r3, uint32_t a) {
    asm volatile("ldmatrix.sync.aligned.m8n8.x4.shared.b16 {%0,%1,%2,%3}, [%4];"
                 : "=r"(r0), "=r"(r1), "=r"(r2), "=r"(r3) : "r"(a));
}
__device__ __forceinline__ void mma_f16(float& c0, float& c1, float& c2, float& c3,
                                        uint32_t a0, uint32_t a1, uint32_t a2, uint32_t a3,
                                        uint32_t b0, uint32_t b1) {
    asm volatile(
        "mma.sync.aligned.m16n8k16.row.col.f32.f16.f16.f32 "
        "{%0,%1,%2,%3}, {%4,%5,%6,%7}, {%8,%9}, {%0,%1,%2,%3};"
        : "+f"(c0), "+f"(c1), "+f"(c2), "+f"(c3)
        : "r"(a0), "r"(a1), "r"(a2), "r"(a3), "r"(b0), "r"(b1));
}
__device__ __forceinline__ void cp16(uint32_t dst, const void* src) {
    asm volatile("cp.async.cg.shared.global [%0], [%1], 16;"
                 :: "r"(dst), "l"(src));
}
#define CP_COMMIT() asm volatile("cp.async.commit_group;" ::: "memory")
#define CP_WAIT1()  asm volatile("cp.async.wait_group 1;" ::: "memory")
#define CP_WAIT0()  asm volatile("cp.async.wait_group 0;" ::: "memory")

// pack code index into 9 low mantissa bits; fmin carries the index for free
__device__ __forceinline__ float encd(float d, int k) {
    return __uint_as_float((__float_as_uint(d) & ~511u) | (uint32_t)k);
}
__device__ __forceinline__ int decd(float v) {
    return (int)(__float_as_uint(v) & 511u);
}
// branchless sorted-quad insert: 7 FMNMX, no predicates
__device__ __forceinline__ void ins4(float d, float& m1, float& m2,
                                     float& m3, float& m4) {
    float t  = fmaxf(m1, d);
    m1 = fminf(m1, d);
    float t2 = fmaxf(m2, t);
    m2 = fminf(m2, t);
    float t3 = fmaxf(m3, t2);
    m3 = fminf(m3, t2);
    m4 = fminf(m4, t3);
}

__device__ __forceinline__ float exact_dist(const float* __restrict__ xp,
                                            const float* __restrict__ emb,
                                            float en2v, int k) {
    const float4* er = (const float4*)(emb + (k << 6));
    float s0 = 0.f, s1 = 0.f, s2 = 0.f, s3 = 0.f;
    #pragma unroll
    for (int c4 = 0; c4 < 16; c4++) {
        float4 e4 = er[c4];
        s0 = fmaf(xp[(c4 * 4 + 0) * HWSZ], e4.x, s0);
        s1 = fmaf(xp[(c4 * 4 + 1) * HWSZ], e4.y, s1);
        s2 = fmaf(xp[(c4 * 4 + 2) * HWSZ], e4.z, s2);
        s3 = fmaf(xp[(c4 * 4 + 3) * HWSZ], e4.w, s3);
    }
    return fmaf(-2.0f, (s0 + s1) + (s2 + s3), en2v);
}

// ---------------- prep: fp16 codebook + en2 + emax + zero hist ----------------
extern "C" __global__ void vq_prep(const float* __restrict__ emb) {
    __shared__ float ws[8];
    const int tid = threadIdx.x;
    const int idx = blockIdx.x * 256 + tid;           // 128 blocks x 256 = 32768
    float e = emb[idx];
    g_Bh[idx] = __half_as_ushort(__float2half_rn(e));
    float v = e * e;
    #pragma unroll
    for (int o = 16; o; o >>= 1) v += __shfl_xor_sync(0xffffffffu, v, o);
    if ((tid & 31) == 0) ws[tid >> 5] = v;
    __syncthreads();
    if (tid < 4) {
        float s = ws[2 * tid] + ws[2 * tid + 1];
        g_en2[blockIdx.x * 4 + tid] = s;
        atomicMax(&g_emax_i, __float_as_int(s));   // positive floats: int order ok
    }
    if (blockIdx.x < 2) g_hist[blockIdx.x * 256 + tid] = 0;
}

// stage one 128-code fp16 chunk (16KB) via cp.async, swizzled
__device__ __forceinline__ void stage_B(uint32_t sbuf, int ch, int tid) {
    const char* src = (const char*)g_Bh + ch * CODES_PER_CHUNK * CDIM * 2;
    #pragma unroll
    for (int t = 0; t < 4; t++) {
        int i = tid + t * 256;                 // 1024 16B units
        int row = i >> 3, cu = (i & 7) * 16;
        cp16(sbuf + row * 128 + (cu ^ ((row & 7) * 16)), src + i * 16);
    }
}

// ---------------- main ----------------
extern "C" __global__ void __launch_bounds__(256, 4)
vq_main(const float* __restrict__ in, const float* __restrict__ emb,
        float* __restrict__ out)
{
    extern __shared__ char smc[];
    const uint32_t sb = s2u(smc);
    const int tid  = threadIdx.x;
    const int lane = tid & 31;
    const int wid  = tid >> 5;

    int*   histS = (int*)(smc + OFF_HIST);
    float* en2s  = (float*)(smc + OFF_EN2);
    float* topv  = (float*)(smc + OFF_TOPV);
    float* xn2s  = (float*)(smc + OFF_XN2);
    int*   winS  = (int*)(smc + OFF_WIN);

    stage_B(sb + OFF_B, 0, tid);
    CP_COMMIT();

    histS[tid] = 0; histS[tid + 256] = 0;
    if (tid < 128) ((float4*)en2s)[tid] = ((const float4*)g_en2)[tid];

    const int pbase = blockIdx.x * TILE_P;

    // ---- stage A: fp16(-2x) swizzled + per-half ||x||^2 partials ----
    {
        const int px   = tid & 127;
        const int half = tid >> 7;
        const int cb   = half * 32;
        const int p    = pbase + px;
        const float* xp = in + (p >> 12) * CHW + (p & (HWSZ - 1));
        float n2 = 0.0f;
        #pragma unroll
        for (int c = cb; c < cb + 32; c += 2) {
            float x0 = xp[c * HWSZ], x1 = xp[(c + 1) * HWSZ];
            n2 = fmaf(x0, x0, n2); n2 = fmaf(x1, x1, n2);
            __half h0 = __float2half_rn(-2.0f * x0);
            __half h1 = __float2half_rn(-2.0f * x1);
            uint32_t hp = (uint32_t)__half_as_ushort(h0) |
                          ((uint32_t)__half_as_ushort(h1) << 16);
            int col = (c * 2) ^ ((px & 7) * 16);
            *(uint32_t*)(smc + OFF_A + px * 128 + col) = hp;
        }
        xn2s[half * 128 + px] = n2;
    }
    __syncthreads();

    // ---- resident A fragments: warp owns pixel rows 16*wid..+15 ----
    uint32_t Ah[4][4];
    {
        const int mtx = lane >> 3;
        const int r   = 16 * wid + (mtx & 1) * 8 + (lane & 7);
        const int kh  = (mtx >> 1) * 16;
        #pragma unroll
        for (int ks = 0; ks < 4; ks++) {
            int col = (ks * 32 + kh) ^ ((r & 7) * 16);
            ldsm_x4(Ah[ks][0], Ah[ks][1], Ah[ks][2], Ah[ks][3],
                    sb + OFF_A + r * 128 + col);
        }
    }

    // ---- sweep: 4 chunks x 8 j-pairs; 1-term fp16 MMA; pair-min + top-4 ----
    float a1 = 3.4e38f, a2 = 3.4e38f, a3 = 3.4e38f, a4 = 3.4e38f;  // row r
    float b1 = 3.4e38f, b2 = 3.4e38f, b3 = 3.4e38f, b4 = 3.4e38f;  // row r+8

    const int btile  = (lane >> 4) & 1;
    const int bkhalf = ((lane >> 3) & 1) * 16;
    const int brow   = lane & 7;

    for (int ch = 0; ch < NCHUNK; ch++) {
        if (ch + 1 < NCHUNK) {
            stage_B(sb + OFF_B + ((ch + 1) & 1) * 16384, ch + 1, tid);
            CP_COMMIT();
            CP_WAIT1();
        } else {
            CP_WAIT0();
        }
        __syncthreads();

        const uint32_t bbase = sb + OFF_B + (ch & 1) * 16384;
        #pragma unroll
        for (int jp = 0; jp < 8; jp++) {          // 16 codes per jp
            const int k0 = ch * CODES_PER_CHUNK + jp * 16 + 2 * (lane & 3);
            float e0, e1, f0, f1;
            asm("ld.shared.v2.f32 {%0,%1}, [%2];"
                : "=f"(e0), "=f"(e1) : "r"(sb + OFF_EN2 + k0 * 4));
            asm("ld.shared.v2.f32 {%0,%1}, [%2];"
                : "=f"(f0), "=f"(f1) : "r"(sb + OFF_EN2 + (k0 + 8) * 4));
            // accumulators pre-loaded with ||e||^2
            float c00 = e0, c01 = e1, c02 = e0, c03 = e1;   // tile 0
            float c10 = f0, c11 = f1, c12 = f0, c13 = f1;   // tile 1
            const int rr = jp * 16 + btile * 8 + brow;
            #pragma unroll
            for (int ks = 0; ks < 4; ks++) {
                int col = (ks * 32 + bkhalf) ^ ((rr & 7) * 16);
                uint32_t h0, h1, h2, h3;
                ldsm_x4(h0, h1, h2, h3, bbase + rr * 128 + col);
                mma_f16(c00, c01, c02, c03, Ah[ks][0], Ah[ks][1], Ah[ks][2], Ah[ks][3], h0, h1);
                mma_f16(c10, c11, c12, c13, Ah[ks][0], Ah[ks][1], Ah[ks][2], Ah[ks][3], h2, h3);
            }
            // pair-min pre-reduction: pairs are adjacent codes {k, k^1}
            float pa0 = fminf(encd(c00, k0),     encd(c01, k0 + 1));
            float pb0 = fminf(encd(c02, k0),     encd(c03, k0 + 1));
            float pa1 = fminf(encd(c10, k0 + 8), encd(c11, k0 + 9));
            float pb1 = fminf(encd(c12, k0 + 8), encd(c13, k0 + 9));
            ins4(pa0, a1, a2, a3, a4);
            ins4(pb0, b1, b2, b3, b4);
            ins4(pa1, a1, a2, a3, a4);
            ins4(pb1, b1, b2, b3, b4);
        }
        __syncthreads();   // all warps done with buf[ch&1] before restage
    }

    // ---- merge quads (of pair minima) across the 4 lanes per accum row ----
    #pragma unroll
    for (int off = 1; off <= 2; off <<= 1) {
        float q1 = __shfl_xor_sync(0xffffffffu, a1, off);
        float q2 = __shfl_xor_sync(0xffffffffu, a2, off);
        float q3 = __shfl_xor_sync(0xffffffffu, a3, off);
        float q4 = __shfl_xor_sync(0xffffffffu, a4, off);
        ins4(q1, a1, a2, a3, a4); ins4(q2, a1, a2, a3, a4);
        ins4(q3, a1, a2, a3, a4); ins4(q4, a1, a2, a3, a4);
        q1 = __shfl_xor_sync(0xffffffffu, b1, off);
        q2 = __shfl_xor_sync(0xffffffffu, b2, off);
        q3 = __shfl_xor_sync(0xffffffffu, b3, off);
        q4 = __shfl_xor_sync(0xffffffffu, b4, off);
        ins4(q1, b1, b2, b3, b4); ins4(q2, b1, b2, b3, b4);
        ins4(q3, b1, b2, b3, b4); ins4(q4, b1, b2, b3, b4);
    }
    if ((lane & 3) == 0) {
        int r0 = 16 * wid + (lane >> 2);
        topv[r0 * 4 + 0] = a1; topv[r0 * 4 + 1] = a2;
        topv[r0 * 4 + 2] = a3; topv[r0 * 4 + 3] = a4;
        int r1 = r0 + 8;
        topv[r1 * 4 + 0] = b1; topv[r1 * 4 + 1] = b2;
        topv[r1 * 4 + 2] = b3; topv[r1 * 4 + 3] = b4;
    }
    __syncthreads();

    // ---- argmin resolution (threads 0..127, one pixel each) ----
    // t1..t4 are the 4 smallest PAIR minima; pair(j) = {j, j^1}.
    if (tid < 128) {
        const int p = pbase + tid;
        const float* xp = in + (p >> 12) * CHW + (p & (HWSZ - 1));
        float t1 = topv[tid * 4 + 0], t2 = topv[tid * 4 + 1];
        float t3 = topv[tid * 4 + 2], t4 = topv[tid * 4 + 3];
        int   j1 = decd(t1), j2 = decd(t2), j3 = decd(t3);

        const float xn2  = xn2s[tid] + xn2s[128 + tid];
        const float em2  = __int_as_float(g_emax_i);
        const float eps  = EPS_C * sqrtf(xn2 * em2) + EPS_M;

        int win;
        if (t4 - t1 >= eps) {
            // winner confined to pairs 1..r where t_{r+1}-t1 >= eps
            int ncand;
            int cand[6];
            cand[0] = j1; cand[1] = j1 ^ 1;
            if (t2 - t1 >= eps) {
                ncand = 2;
            } else if (t3 - t1 >= eps) {
                cand[2] = j2; cand[3] = j2 ^ 1; ncand = 4;
            } else {
                cand[2] = j2; cand[3] = j2 ^ 1;
                cand[4] = j3; cand[5] = j3 ^ 1; ncand = 6;
            }
            float bd = 3.4e38f; win = 0;
            for (int c = 0; c < ncand; c++) {
                int k = cand[c];
                float dv = exact_dist(xp, emb, en2s[k], k);
                if (dv < bd || (dv == bd && k < win)) { bd = dv; win = k; }
            }
        } else {
            win = -1;                          // rare: full exact scan
        }
        unsigned m = __ballot_sync(0xffffffffu, win < 0);
        while (m) {
            int src = __ffs(m) - 1; m &= m - 1;
            int pp = __shfl_sync(0xffffffffu, p, src);
            const float* xq = in + (pp >> 12) * CHW + (pp & (HWSZ - 1));
            float bd = 3.4e38f; int bi = 0;
            for (int kk = lane; kk < KCODES; kk += 32) {
                float dv = exact_dist(xq, emb, en2s[kk], kk);
                if (dv < bd || (dv == bd && kk < bi)) { bd = dv; bi = kk; }
            }
            #pragma unroll
            for (int o = 16; o; o >>= 1) {
                float od = __shfl_xor_sync(0xffffffffu, bd, o);
                int   oi = __shfl_xor_sync(0xffffffffu, bi, o);
                if (od < bd || (od == bd && oi < bi)) { bd = od; bi = oi; }
            }
            if (lane == src) win = bi;
        }

        winS[tid] = win;
        atomicAdd(&histS[win], 1);
        out[OUT_IDX_OFF + p] = (float)win;
    }
    __syncthreads();

    // ---- scatter + loss on all 256 threads (2 per pixel) ----
    float lossLocal = 0.0f;
    {
        const int px   = tid & 127;
        const int half = tid >> 7;
        const int p    = pbase + px;
        const int win  = winS[px];
        const float* xp = in  + (p >> 12) * CHW + (p & (HWSZ - 1)) + half * 32 * HWSZ;
        float*       op = out + (p >> 12) * CHW + (p & (HWSZ - 1)) + half * 32 * HWSZ;
        const float4* qr = (const float4*)(emb + (win << 6) + half * 32);
        #pragma unroll
        for (int c4 = 0; c4 < 8; c4++) {
            float4 q4 = qr[c4];
            float x0 = xp[(c4 * 4 + 0) * HWSZ];
            float x1 = xp[(c4 * 4 + 1) * HWSZ];
            float x2 = xp[(c4 * 4 + 2) * HWSZ];
            float x3 = xp[(c4 * 4 + 3) * HWSZ];
            op[(c4 * 4 + 0) * HWSZ] = q4.x;
            op[(c4 * 4 + 1) * HWSZ] = q4.y;
            op[(c4 * 4 + 2) * HWSZ] = q4.z;
            op[(c4 * 4 + 3) * HWSZ] = q4.w;
            float e0 = q4.x - x0, e1 = q4.y - x1, e2 = q4.z - x2, e3 = q4.w - x3;
            lossLocal += e0 * e0 + e1 * e1 + e2 * e2 + e3 * e3;
        }
    }
    #pragma unroll
    for (int o = 16; o; o >>= 1)
        lossLocal += __shfl_xor_sync(0xffffffffu, lossLocal, o);
    if (lane == 0) ((float*)(smc + OFF_WS))[wid] = lossLocal;
    __syncthreads();
    if (tid == 0) {
        float* ws = (float*)(smc + OFF_WS);
        g_part[blockIdx.x] = ((ws[0] + ws[1]) + (ws[2] + ws[3]))
                           + ((ws[4] + ws[5]) + (ws[6] + ws[7]));
    }
    atomicAdd(&g_hist[tid],       histS[tid]);
    atomicAdd(&g_hist[tid + 256], histS[tid + 256]);
}

// ---------------- final: scalars ----------------
extern "C" __global__ void vq_final(const float* __restrict__ w,
                                    float* __restrict__ out)
{
    __shared__ float red[KCODES];
    const int t = threadIdx.x;

    float pv = (float)g_hist[t] * (1.0f / (float)N_PIX);
    red[t] = pv * logf(pv + 1e-10f);
    __syncthreads();
    #pragma unroll
    for (int s = KCODES / 2; s > 0; s >>= 1) {
        if (t < s) red[t] += red[t + s];
        __syncthreads();
    }
    float perp = 0.0f;
    if (t == 0) perp = expf(-red[0]);
    __syncthreads();

    red[t] = (w[t] >= 0.01f) ? 1.0f : 0.0f;
    __syncthreads();
    #pragma unroll
    for (int s = KCODES / 2; s > 0; s >>= 1) {
        if (t < s) red[t] += red[t + s];
        __syncthreads();
    }
    float act = 0.0f;
    if (t == 0) act = red[0];
    __syncthreads();

    red[t] = (t < NBLK) ? g_part[t] : 0.0f;
    __syncthreads();
    #pragma unroll
    for (int s = KCODES / 2; s > 0; s >>= 1) {
        if (t < s) red[t] += red[t + s];
        __syncthreads();
    }
    if (t == 0) {
        out[OUT_LOSS_OFF] = red[0] * (1.0f / ((float)N_PIX * (float)CDIM));
        out[OUT_PERP_OFF] = perp;
        out[OUT_ACT_OFF]  = act;
    }
}

extern "C" void kernel_launch(void* const* d_in, const int* in_sizes, int n_in,
                              void* d_out, int out_size)
{
    const float* in  = (const float*)d_in[0];
    const float* emb = (const float*)d_in[1];
    const float* w   = (const float*)d_in[2];
    float* out = (float*)d_out;

    cudaFuncSetAttribute(vq_main, cudaFuncAttributeMaxDynamicSharedMemorySize,
                         SMEM_MAIN);

    vq_prep<<<128, 256>>>(emb);
    vq_main<<<NBLK, 256, SMEM_MAIN>>>(in, emb, out);
    vq_final<<<1, KCODES>>>(w, out);
}

// round 15
// speedup vs baseline: 1.0290x; 1.0290x over previous
#include <cuda_runtime.h>
#include <cuda_fp16.h>
#include <cstdint>

// ---------------- problem constants ----------------
#define N_PIX   65536
#define CDIM    64
#define KCODES  512
#define HWSZ    4096
#define CHW     (CDIM * HWSZ)

#define OUT_Q_ELEMS  (N_PIX * CDIM)
#define OUT_LOSS_OFF OUT_Q_ELEMS
#define OUT_PERP_OFF (OUT_Q_ELEMS + 1)
#define OUT_ACT_OFF  (OUT_Q_ELEMS + 2)
#define OUT_IDX_OFF  (OUT_Q_ELEMS + 3)

#define TILE_P   128
#define NBLK     (N_PIX / TILE_P)      // 512
#define CODES_PER_CHUNK 128
#define NCHUNK   (KCODES / CODES_PER_CHUNK)   // 4

// eps_p = EPS_C * ||x_p|| * max||e|| + EPS_M   (rigorous 1-term fp16 bound)
#define EPS_C 4.1e-3f
#define EPS_M 0.07f

// ---------------- device scratch ----------------
__device__ __align__(16) uint16_t g_Bh[KCODES * CDIM];   // fp16 codebook
__device__ __align__(16) float    g_en2[KCODES];
__device__ int   g_emax_i = 0;                            // max en2 as int bits
__device__ int   g_hist[KCODES];
__device__ float g_part[NBLK];

// ---------------- smem layout ----------------
#define OFF_A     0          // 16384: fp16(-2x), 128 rows x 128B swizzled
#define OFF_B     16384      // 2 x 16384 double buffer (128 codes x 128B)
                             // after sweep: fp32 x tile, channel-major [c*128+px]
#define OFF_EN2   49152      // 2048
#define OFF_TOPV  51200      // 2048: 128 x 4 floats (pair minima, idx packed)
#define OFF_HIST  53248      // 2048
#define OFF_XN2   55296      // 1024: 2 halves x 128 partial ||x||^2
#define OFF_WIN   56320      // 512
#define OFF_WS    56832      // 32
#define SMEM_MAIN 56864

// ---------------- PTX helpers (compute_103-legal only) ----------------
__device__ __forceinline__ uint32_t s2u(const void* p) {
    uint32_t a;
    asm("{ .reg .u64 t; cvta.to.shared.u64 t, %1; cvt.u32.u64 %0, t; }"
        : "=r"(a) : "l"(p));
    return a;
}
__device__ __forceinline__ void ldsm_x4(uint32_t& r0, uint32_t& r1,
                                        uint32_t& r2, uint32_t& r3, uint32_t a) {
    asm volatile("ldmatrix.sync.aligned.m8n8.x4.shared.b16 {%0,%1,%2,%3}, [%4];"
                 : "=r"(r0), "=r"(r1), "=r"(r2), "=r"(r3) : "r"(a));
}
__device__ __forceinline__ void mma_f16(float& c0, float& c1, float& c2, float& c3,
                                        uint32_t a0, uint32_t a1, uint32_t a2, uint32_t a3,
                                        uint32_t b0, uint32_t b1) {
    asm volatile(
        "mma.sync.aligned.m16n8k16.row.col.f32.f16.f16.f32 "
        "{%0,%1,%2,%3}, {%4,%5,%6,%7}, {%8,%9}, {%0,%1,%2,%3};"
        : "+f"(c0), "+f"(c1), "+f"(c2), "+f"(c3)
        : "r"(a0), "r"(a1), "r"(a2), "r"(a3), "r"(b0), "r"(b1));
}
__device__ __forceinline__ void cp16(uint32_t dst, const void* src) {
    asm volatile("cp.async.cg.shared.global [%0], [%1], 16;"
                 :: "r"(dst), "l"(src));
}
#define CP_COMMIT() asm volatile("cp.async.commit_group;" ::: "memory")
#define CP_WAIT1()  asm volatile("cp.async.wait_group 1;" ::: "memory")
#define CP_WAIT0()  asm volatile("cp.async.wait_group 0;" ::: "memory")

// pack code index into 9 low mantissa bits; fmin carries the index for free
__device__ __forceinline__ float encd(float d, int k) {
    return __uint_as_float((__float_as_uint(d) & ~511u) | (uint32_t)k);
}
__device__ __forceinline__ int decd(float v) {
    return (int)(__float_as_uint(v) & 511u);
}
// branchless sorted-quad insert: 7 FMNMX, no predicates
__device__ __forceinline__ void ins4(float d, float& m1, float& m2,
                                     float& m3, float& m4) {
    float t  = fmaxf(m1, d);
    m1 = fminf(m1, d);
    float t2 = fmaxf(m2, t);
    m2 = fminf(m2, t);
    float t3 = fmaxf(m3, t2);
    m3 = fminf(m3, t2);
    m4 = fminf(m4, t3);
}

// exact fp32 distance with x cached in smem (channel-major xs[c*128+px])
__device__ __forceinline__ float exact_dist_s(const float* __restrict__ xs,
                                              int px,
                                              const float* __restrict__ emb,
                                              float en2v, int k) {
    const float4* er = (const float4*)(emb + (k << 6));
    float s0 = 0.f, s1 = 0.f, s2 = 0.f, s3 = 0.f;
    #pragma unroll
    for (int c4 = 0; c4 < 16; c4++) {
        float4 e4 = er[c4];
        s0 = fmaf(xs[(c4 * 4 + 0) * 128 + px], e4.x, s0);
        s1 = fmaf(xs[(c4 * 4 + 1) * 128 + px], e4.y, s1);
        s2 = fmaf(xs[(c4 * 4 + 2) * 128 + px], e4.z, s2);
        s3 = fmaf(xs[(c4 * 4 + 3) * 128 + px], e4.w, s3);
    }
    return fmaf(-2.0f, (s0 + s1) + (s2 + s3), en2v);
}

// ---------------- prep: fp16 codebook + en2 + emax + zero hist ----------------
extern "C" __global__ void vq_prep(const float* __restrict__ emb) {
    __shared__ float ws[8];
    const int tid = threadIdx.x;
    const int idx = blockIdx.x * 256 + tid;           // 128 blocks x 256 = 32768
    float e = emb[idx];
    g_Bh[idx] = __half_as_ushort(__float2half_rn(e));
    float v = e * e;
    #pragma unroll
    for (int o = 16; o; o >>= 1) v += __shfl_xor_sync(0xffffffffu, v, o);
    if ((tid & 31) == 0) ws[tid >> 5] = v;
    __syncthreads();
    if (tid < 4) {
        float s = ws[2 * tid] + ws[2 * tid + 1];
        g_en2[blockIdx.x * 4 + tid] = s;
        atomicMax(&g_emax_i, __float_as_int(s));   // positive floats: int order ok
    }
    if (blockIdx.x < 2) g_hist[blockIdx.x * 256 + tid] = 0;
}

// stage one 128-code fp16 chunk (16KB) via cp.async, swizzled
__device__ __forceinline__ void stage_B(uint32_t sbuf, int ch, int tid) {
    const char* src = (const char*)g_Bh + ch * CODES_PER_CHUNK * CDIM * 2;
    #pragma unroll
    for (int t = 0; t < 4; t++) {
        int i = tid + t * 256;                 // 1024 16B units
        int row = i >> 3, cu = (i & 7) * 16;
        cp16(sbuf + row * 128 + (cu ^ ((row & 7) * 16)), src + i * 16);
    }
}

// ---------------- main ----------------
extern "C" __global__ void __launch_bounds__(256, 4)
vq_main(const float* __restrict__ in, const float* __restrict__ emb,
        float* __restrict__ out)
{
    extern __shared__ char smc[];
    const uint32_t sb = s2u(smc);
    const int tid  = threadIdx.x;
    const int lane = tid & 31;
    const int wid  = tid >> 5;

    int*   histS = (int*)(smc + OFF_HIST);
    float* en2s  = (float*)(smc + OFF_EN2);
    float* topv  = (float*)(smc + OFF_TOPV);
    float* xn2s  = (float*)(smc + OFF_XN2);
    int*   winS  = (int*)(smc + OFF_WIN);

    stage_B(sb + OFF_B, 0, tid);
    CP_COMMIT();

    histS[tid] = 0; histS[tid + 256] = 0;
    if (tid < 128) ((float4*)en2s)[tid] = ((const float4*)g_en2)[tid];

    const int pbase = blockIdx.x * TILE_P;
    // CTA's 128 pixels live in one image: base gmem offset for (px=0, c=0)
    const int gbase = ((pbase >> 12) * CDIM) * HWSZ + (pbase & (HWSZ - 1));

    // ---- stage A: fp16(-2x) swizzled + per-half ||x||^2 partials ----
    {
        const int px   = tid & 127;
        const int half = tid >> 7;
        const int cb   = half * 32;
        const float* xp = in + gbase + px;
        float n2 = 0.0f;
        #pragma unroll
        for (int c = cb; c < cb + 32; c += 2) {
            float x0 = xp[c * HWSZ], x1 = xp[(c + 1) * HWSZ];
            n2 = fmaf(x0, x0, n2); n2 = fmaf(x1, x1, n2);
            __half h0 = __float2half_rn(-2.0f * x0);
            __half h1 = __float2half_rn(-2.0f * x1);
            uint32_t hp = (uint32_t)__half_as_ushort(h0) |
                          ((uint32_t)__half_as_ushort(h1) << 16);
            int col = (c * 2) ^ ((px & 7) * 16);
            *(uint32_t*)(smc + OFF_A + px * 128 + col) = hp;
        }
        xn2s[half * 128 + px] = n2;
    }
    __syncthreads();

    // ---- resident A fragments: warp owns pixel rows 16*wid..+15 ----
    uint32_t Ah[4][4];
    {
        const int mtx = lane >> 3;
        const int r   = 16 * wid + (mtx & 1) * 8 + (lane & 7);
        const int kh  = (mtx >> 1) * 16;
        #pragma unroll
        for (int ks = 0; ks < 4; ks++) {
            int col = (ks * 32 + kh) ^ ((r & 7) * 16);
            ldsm_x4(Ah[ks][0], Ah[ks][1], Ah[ks][2], Ah[ks][3],
                    sb + OFF_A + r * 128 + col);
        }
    }

    // ---- sweep: 4 chunks x 8 j-pairs; 1-term fp16 MMA; pair-min + top-4 ----
    float a1 = 3.4e38f, a2 = 3.4e38f, a3 = 3.4e38f, a4 = 3.4e38f;  // row r
    float b1 = 3.4e38f, b2 = 3.4e38f, b3 = 3.4e38f, b4 = 3.4e38f;  // row r+8

    const int btile  = (lane >> 4) & 1;
    const int bkhalf = ((lane >> 3) & 1) * 16;
    const int brow   = lane & 7;

    for (int ch = 0; ch < NCHUNK; ch++) {
        if (ch + 1 < NCHUNK) {
            stage_B(sb + OFF_B + ((ch + 1) & 1) * 16384, ch + 1, tid);
            CP_COMMIT();
            CP_WAIT1();
        } else {
            CP_WAIT0();
        }
        __syncthreads();

        const uint32_t bbase = sb + OFF_B + (ch & 1) * 16384;
        #pragma unroll
        for (int jp = 0; jp < 8; jp++) {          // 16 codes per jp
            const int k0 = ch * CODES_PER_CHUNK + jp * 16 + 2 * (lane & 3);
            float e0, e1, f0, f1;
            asm("ld.shared.v2.f32 {%0,%1}, [%2];"
                : "=f"(e0), "=f"(e1) : "r"(sb + OFF_EN2 + k0 * 4));
            asm("ld.shared.v2.f32 {%0,%1}, [%2];"
                : "=f"(f0), "=f"(f1) : "r"(sb + OFF_EN2 + (k0 + 8) * 4));
            // accumulators pre-loaded with ||e||^2
            float c00 = e0, c01 = e1, c02 = e0, c03 = e1;   // tile 0
            float c10 = f0, c11 = f1, c12 = f0, c13 = f1;   // tile 1
            const int rr = jp * 16 + btile * 8 + brow;
            #pragma unroll
            for (int ks = 0; ks < 4; ks++) {
                int col = (ks * 32 + bkhalf) ^ ((rr & 7) * 16);
                uint32_t h0, h1, h2, h3;
                ldsm_x4(h0, h1, h2, h3, bbase + rr * 128 + col);
                mma_f16(c00, c01, c02, c03, Ah[ks][0], Ah[ks][1], Ah[ks][2], Ah[ks][3], h0, h1);
                mma_f16(c10, c11, c12, c13, Ah[ks][0], Ah[ks][1], Ah[ks][2], Ah[ks][3], h2, h3);
            }
            // pair-min pre-reduction: pairs are adjacent codes {k, k^1}
            float pa0 = fminf(encd(c00, k0),     encd(c01, k0 + 1));
            float pb0 = fminf(encd(c02, k0),     encd(c03, k0 + 1));
            float pa1 = fminf(encd(c10, k0 + 8), encd(c11, k0 + 9));
            float pb1 = fminf(encd(c12, k0 + 8), encd(c13, k0 + 9));
            ins4(pa0, a1, a2, a3, a4);
            ins4(pb0, b1, b2, b3, b4);
            ins4(pa1, a1, a2, a3, a4);
            ins4(pb1, b1, b2, b3, b4);
        }
        __syncthreads();   // all warps done with buf[ch&1] before restage
    }

    // ---- merge quads (of pair minima) across the 4 lanes per accum row ----
    #pragma unroll
    for (int off = 1; off <= 2; off <<= 1) {
        float q1 = __shfl_xor_sync(0xffffffffu, a1, off);
        float q2 = __shfl_xor_sync(0xffffffffu, a2, off);
        float q3 = __shfl_xor_sync(0xffffffffu, a3, off);
        float q4 = __shfl_xor_sync(0xffffffffu, a4, off);
        ins4(q1, a1, a2, a3, a4); ins4(q2, a1, a2, a3, a4);
        ins4(q3, a1, a2, a3, a4); ins4(q4, a1, a2, a3, a4);
        q1 = __shfl_xor_sync(0xffffffffu, b1, off);
        q2 = __shfl_xor_sync(0xffffffffu, b2, off);
        q3 = __shfl_xor_sync(0xffffffffu, b3, off);
        q4 = __shfl_xor_sync(0xffffffffu, b4, off);
        ins4(q1, b1, b2, b3, b4); ins4(q2, b1, b2, b3, b4);
        ins4(q3, b1, b2, b3, b4); ins4(q4, b1, b2, b3, b4);
    }
    if ((lane & 3) == 0) {
        int r0 = 16 * wid + (lane >> 2);
        topv[r0 * 4 + 0] = a1; topv[r0 * 4 + 1] = a2;
        topv[r0 * 4 + 2] = a3; topv[r0 * 4 + 3] = a4;
        int r1 = r0 + 8;
        topv[r1 * 4 + 0] = b1; topv[r1 * 4 + 1] = b2;
        topv[r1 * 4 + 2] = b3; topv[r1 * 4 + 3] = b4;
    }

    // ---- load fp32 x tile into the dead B buffer, channel-major (coalesced) ----
    float* xs = (float*)(smc + OFF_B);
    {
        // i = c*128 + px; consecutive tid -> consecutive px -> coalesced gmem
        #pragma unroll
        for (int t = 0; t < 32; t++) {
            int i  = tid + t * 256;            // 8192 elements
            int px = i & 127, c = i >> 7;
            xs[i] = in[gbase + c * HWSZ + px];
        }
    }
    __syncthreads();

    // ---- argmin resolution (threads 0..127, one pixel each) ----
    // t1..t4 are the 4 smallest PAIR minima; pair(j) = {j, j^1}.
    if (tid < 128) {
        const int px = tid;
        float t1 = topv[px * 4 + 0], t2 = topv[px * 4 + 1];
        float t3 = topv[px * 4 + 2], t4 = topv[px * 4 + 3];
        int   j1 = decd(t1), j2 = decd(t2), j3 = decd(t3);

        const float xn2  = xn2s[px] + xn2s[128 + px];
        const float em2  = __int_as_float(g_emax_i);
        const float eps  = EPS_C * sqrtf(xn2 * em2) + EPS_M;

        int win;
        if (t4 - t1 >= eps) {
            // winner confined to pairs 1..r where t_{r+1}-t1 >= eps
            int ncand;
            int cand[6];
            cand[0] = j1; cand[1] = j1 ^ 1;
            if (t2 - t1 >= eps) {
                ncand = 2;
            } else if (t3 - t1 >= eps) {
                cand[2] = j2; cand[3] = j2 ^ 1; ncand = 4;
            } else {
                cand[2] = j2; cand[3] = j2 ^ 1;
                cand[4] = j3; cand[5] = j3 ^ 1; ncand = 6;
            }
            float bd = 3.4e38f; win = 0;
            for (int c = 0; c < ncand; c++) {
                int k = cand[c];
                float dv = exact_dist_s(xs, px, emb, en2s[k], k);
                if (dv < bd || (dv == bd && k < win)) { bd = dv; win = k; }
            }
        } else {
            win = -1;                          // rare: full exact scan
        }
        unsigned m = __ballot_sync(0xffffffffu, win < 0);
        while (m) {
            int src = __ffs(m) - 1; m &= m - 1;
            int pp = __shfl_sync(0xffffffffu, px, src);
            float bd = 3.4e38f; int bi = 0;
            for (int kk = lane; kk < KCODES; kk += 32) {
                float dv = exact_dist_s(xs, pp, emb, en2s[kk], kk);
                if (dv < bd || (dv == bd && kk < bi)) { bd = dv; bi = kk; }
            }
            #pragma unroll
            for (int o = 16; o; o >>= 1) {
                float od = __shfl_xor_sync(0xffffffffu, bd, o);
                int   oi = __shfl_xor_sync(0xffffffffu, bi, o);
                if (od < bd || (od == bd && oi < bi)) { bd = od; bi = oi; }
            }
            if (lane == src) win = bi;
        }

        winS[px] = win;
        atomicAdd(&histS[win], 1);
        out[OUT_IDX_OFF + pbase + px] = (float)win;
    }
    __syncthreads();

    // ---- scatter + loss on all 256 threads (2 per pixel), x from smem ----
    float lossLocal = 0.0f;
    {
        const int px   = tid & 127;
        const int half = tid >> 7;
        const int win  = winS[px];
        float*       op = out + gbase + px + half * 32 * HWSZ;
        const float4* qr = (const float4*)(emb + (win << 6) + half * 32);
        const float* xr = xs + half * 32 * 128 + px;
        #pragma unroll
        for (int c4 = 0; c4 < 8; c4++) {
            float4 q4 = qr[c4];
            float x0 = xr[(c4 * 4 + 0) * 128];
            float x1 = xr[(c4 * 4 + 1) * 128];
            float x2 = xr[(c4 * 4 + 2) * 128];
            float x3 = xr[(c4 * 4 + 3) * 128];
            op[(c4 * 4 + 0) * HWSZ] = q4.x;
            op[(c4 * 4 + 1) * HWSZ] = q4.y;
            op[(c4 * 4 + 2) * HWSZ] = q4.z;
            op[(c4 * 4 + 3) * HWSZ] = q4.w;
            float e0 = q4.x - x0, e1 = q4.y - x1, e2 = q4.z - x2, e3 = q4.w - x3;
            lossLocal += e0 * e0 + e1 * e1 + e2 * e2 + e3 * e3;
        }
    }
    #pragma unroll
    for (int o = 16; o; o >>= 1)
        lossLocal += __shfl_xor_sync(0xffffffffu, lossLocal, o);
    if (lane == 0) ((float*)(smc + OFF_WS))[wid] = lossLocal;
    __syncthreads();
    if (tid == 0) {
        float* ws = (float*)(smc + OFF_WS);
        g_part[blockIdx.x] = ((ws[0] + ws[1]) + (ws[2] + ws[3]))
                           + ((ws[4] + ws[5]) + (ws[6] + ws[7]));
    }
    atomicAdd(&g_hist[tid],       histS[tid]);
    atomicAdd(&g_hist[tid + 256], histS[tid + 256]);
}

// ---------------- final: scalars ----------------
extern "C" __global__ void vq_final(const float* __restrict__ w,
                                    float* __restrict__ out)
{
    __shared__ float red[KCODES];
    const int t = threadIdx.x;

    float pv = (float)g_hist[t] * (1.0f / (float)N_PIX);
    red[t] = pv * logf(pv + 1e-10f);
    __syncthreads();
    #pragma unroll
    for (int s = KCODES / 2; s > 0; s >>= 1) {
        if (t < s) red[t] += red[t + s];
        __syncthreads();
    }
    float perp = 0.0f;
    if (t == 0) perp = expf(-red[0]);
    __syncthreads();

    red[t] = (w[t] >= 0.01f) ? 1.0f : 0.0f;
    __syncthreads();
    #pragma unroll
    for (int s = KCODES / 2; s > 0; s >>= 1) {
        if (t < s) red[t] += red[t + s];
        __syncthreads();
    }
    float act = 0.0f;
    if (t == 0) act = red[0];
    __syncthreads();

    red[t] = (t < NBLK) ? g_part[t] : 0.0f;
    __syncthreads();
    #pragma unroll
    for (int s = KCODES / 2; s > 0; s >>= 1) {
        if (t < s) red[t] += red[t + s];
        __syncthreads();
    }
    if (t == 0) {
        out[OUT_LOSS_OFF] = red[0] * (1.0f / ((float)N_PIX * (float)CDIM));
        out[OUT_PERP_OFF] = perp;
        out[OUT_ACT_OFF]  = act;
    }
}

extern "C" void kernel_launch(void* const* d_in, const int* in_sizes, int n_in,
                              void* d_out, int out_size)
{
    const float* in  = (const float*)d_in[0];
    const float* emb = (const float*)d_in[1];
    const float* w   = (const float*)d_in[2];
    float* out = (float*)d_out;

    cudaFuncSetAttribute(vq_main, cudaFuncAttributeMaxDynamicSharedMemorySize,
                         SMEM_MAIN);

    vq_prep<<<128, 256>>>(emb);
    vq_main<<<NBLK, 256, SMEM_MAIN>>>(in, emb, out);
    vq_final<<<1, KCODES>>>(w, out);
}

// round 17
// speedup vs baseline: 1.1604x; 1.1277x over previous
#include <cuda_runtime.h>
#include <cuda_fp16.h>
#include <cstdint>

// ---------------- problem constants ----------------
#define N_PIX   65536
#define CDIM    64
#define KCODES  512
#define HWSZ    4096
#define CHW     (CDIM * HWSZ)

#define OUT_Q_ELEMS  (N_PIX * CDIM)
#define OUT_LOSS_OFF OUT_Q_ELEMS
#define OUT_PERP_OFF (OUT_Q_ELEMS + 1)
#define OUT_ACT_OFF  (OUT_Q_ELEMS + 2)
#define OUT_IDX_OFF  (OUT_Q_ELEMS + 3)

#define TILE_P   64
#define THREADS  128
#define NBLK     (N_PIX / TILE_P)      // 1024
#define CODES_PER_CHUNK 64
#define NCHUNK   (KCODES / CODES_PER_CHUNK)   // 8

// eps_p = EPS_C * ||x_p|| * max||e|| + EPS_M   (rigorous 1-term fp16 bound)
#define EPS_C 4.1e-3f
#define EPS_M 0.07f

// ---------------- device scratch ----------------
__device__ __align__(16) uint16_t g_Bh[KCODES * CDIM];   // fp16 codebook
__device__ __align__(16) float    g_en2[KCODES];
__device__ int   g_emax_i = 0;                            // max en2 as int bits
__device__ int   g_hist[KCODES];
__device__ float g_part[NBLK];

// ---------------- smem layout (per CTA, ~30.6 KB) ----------------
#define OFF_A     0          // 8192: fp16(-2x), 64 rows x 128B swizzled
#define OFF_B     8192       // 2 x 8192 double buffer (64 codes x 128B)
#define OFF_EN2   24576      // 2048
#define OFF_TOPV  26624      // 1024: 64 x 4 floats (idx packed in mantissa)
#define OFF_HIST  27648      // 2048
#define OFF_XN2   29696      // 512: 2 halves x 64 partial ||x||^2
#define OFF_WIN   30208      // 256
#define OFF_WS    30464      // 16
#define SMEM_MAIN 30480

// ---------------- PTX helpers (compute_103-legal only) ----------------
__device__ __forceinline__ uint32_t s2u(const void* p) {
    uint32_t a;
    asm("{ .reg .u64 t; cvta.to.shared.u64 t, %1; cvt.u32.u64 %0, t; }"
        : "=r"(a) : "l"(p));
    return a;
}
__device__ __forceinline__ void ldsm_x4(uint32_t& r0, uint32_t& r1,
                                        uint32_t& r2, uint32_t& r3, uint32_t a) {
    asm volatile("ldmatrix.sync.aligned.m8n8.x4.shared.b16 {%0,%1,%2,%3}, [%4];"
                 : "=r"(r0), "=r"(r1), "=r"(r2), "=r"(r3) : "r"(a));
}
__device__ __forceinline__ void mma_f16(float& c0, float& c1, float& c2, float& c3,
                                        uint32_t a0, uint32_t a1, uint32_t a2, uint32_t a3,
                                        uint32_t b0, uint32_t b1) {
    asm volatile(
        "mma.sync.aligned.m16n8k16.row.col.f32.f16.f16.f32 "
        "{%0,%1,%2,%3}, {%4,%5,%6,%7}, {%8,%9}, {%0,%1,%2,%3};"
        : "+f"(c0), "+f"(c1), "+f"(c2), "+f"(c3)
        : "r"(a0), "r"(a1), "r"(a2), "r"(a3), "r"(b0), "r"(b1));
}
__device__ __forceinline__ void cp16(uint32_t dst, const void* src) {
    asm volatile("cp.async.cg.shared.global [%0], [%1], 16;"
                 :: "r"(dst), "l"(src));
}
#define CP_COMMIT() asm volatile("cp.async.commit_group;" ::: "memory")
#define CP_WAIT1()  asm volatile("cp.async.wait_group 1;" ::: "memory")
#define CP_WAIT0()  asm volatile("cp.async.wait_group 0;" ::: "memory")

// pack code index into 9 low mantissa bits; fmin carries the index for free
__device__ __forceinline__ float encd(float d, int k) {
    return __uint_as_float((__float_as_uint(d) & ~511u) | (uint32_t)k);
}
__device__ __forceinline__ int decd(float v) {
    return (int)(__float_as_uint(v) & 511u);
}
// branchless sorted-quad insert: 7 FMNMX, no predicates
__device__ __forceinline__ void ins4(float d, float& m1, float& m2,
                                     float& m3, float& m4) {
    float t  = fmaxf(m1, d);
    m1 = fminf(m1, d);
    float t2 = fmaxf(m2, t);
    m2 = fminf(m2, t);
    float t3 = fmaxf(m3, t2);
    m3 = fminf(m3, t2);
    m4 = fminf(m4, t3);
}

__device__ __forceinline__ float exact_dist(const float* __restrict__ xp,
                                            const float* __restrict__ emb,
                                            float en2v, int k) {
    const float4* er = (const float4*)(emb + (k << 6));
    float s0 = 0.f, s1 = 0.f, s2 = 0.f, s3 = 0.f;
    #pragma unroll
    for (int c4 = 0; c4 < 16; c4++) {
        float4 e4 = er[c4];
        s0 = fmaf(xp[(c4 * 4 + 0) * HWSZ], e4.x, s0);
        s1 = fmaf(xp[(c4 * 4 + 1) * HWSZ], e4.y, s1);
        s2 = fmaf(xp[(c4 * 4 + 2) * HWSZ], e4.z, s2);
        s3 = fmaf(xp[(c4 * 4 + 3) * HWSZ], e4.w, s3);
    }
    return fmaf(-2.0f, (s0 + s1) + (s2 + s3), en2v);
}

// ---------------- prep: fp16 codebook + en2 + emax + zero hist ----------------
extern "C" __global__ void vq_prep(const float* __restrict__ emb) {
    __shared__ float ws[8];
    const int tid = threadIdx.x;
    const int idx = blockIdx.x * 256 + tid;           // 128 blocks x 256 = 32768
    float e = emb[idx];
    g_Bh[idx] = __half_as_ushort(__float2half_rn(e));
    float v = e * e;
    #pragma unroll
    for (int o = 16; o; o >>= 1) v += __shfl_xor_sync(0xffffffffu, v, o);
    if ((tid & 31) == 0) ws[tid >> 5] = v;
    __syncthreads();
    if (tid < 4) {
        float s = ws[2 * tid] + ws[2 * tid + 1];
        g_en2[blockIdx.x * 4 + tid] = s;
        atomicMax(&g_emax_i, __float_as_int(s));   // positive floats: int order ok
    }
    if (blockIdx.x < 2) g_hist[blockIdx.x * 256 + tid] = 0;
}

// stage one 64-code fp16 chunk (8KB) via cp.async, swizzled
__device__ __forceinline__ void stage_B(uint32_t sbuf, int ch, int tid) {
    const char* src = (const char*)g_Bh + ch * CODES_PER_CHUNK * CDIM * 2;
    #pragma unroll
    for (int t = 0; t < 4; t++) {
        int i = tid + t * THREADS;             // 512 16B units
        int row = i >> 3, cu = (i & 7) * 16;
        cp16(sbuf + row * 128 + (cu ^ ((row & 7) * 16)), src + i * 16);
    }
}

// ---------------- main ----------------
extern "C" __global__ void __launch_bounds__(THREADS, 7)
vq_main(const float* __restrict__ in, const float* __restrict__ emb,
        float* __restrict__ out)
{
    extern __shared__ char smc[];
    const uint32_t sb = s2u(smc);
    const int tid  = threadIdx.x;
    const int lane = tid & 31;
    const int wid  = tid >> 5;               // 0..3

    int*   histS = (int*)(smc + OFF_HIST);
    float* en2s  = (float*)(smc + OFF_EN2);
    float* topv  = (float*)(smc + OFF_TOPV);
    float* xn2s  = (float*)(smc + OFF_XN2);
    int*   winS  = (int*)(smc + OFF_WIN);

    stage_B(sb + OFF_B, 0, tid);
    CP_COMMIT();

    #pragma unroll
    for (int t = 0; t < 4; t++) histS[tid + t * THREADS] = 0;
    ((float4*)en2s)[tid] = ((const float4*)g_en2)[tid];   // 128 x float4 = 512

    const int pbase = blockIdx.x * TILE_P;
    // all 64 pixels of a tile lie in one image row-block (64 | 4096)
    const int p0 = pbase;

    // ---- stage A: fp16(-2x) swizzled + per-half ||x||^2 partials ----
    {
        const int px   = tid & 63;
        const int half = tid >> 6;
        const int cb   = half * 32;
        const int p    = p0 + px;
        const float* xp = in + (p >> 12) * CHW + (p & (HWSZ - 1));
        float n2 = 0.0f;
        #pragma unroll
        for (int c = cb; c < cb + 32; c += 2) {
            float x0 = xp[c * HWSZ], x1 = xp[(c + 1) * HWSZ];
            n2 = fmaf(x0, x0, n2); n2 = fmaf(x1, x1, n2);
            __half h0 = __float2half_rn(-2.0f * x0);
            __half h1 = __float2half_rn(-2.0f * x1);
            uint32_t hp = (uint32_t)__half_as_ushort(h0) |
                          ((uint32_t)__half_as_ushort(h1) << 16);
            int col = (c * 2) ^ ((px & 7) * 16);
            *(uint32_t*)(smc + OFF_A + px * 128 + col) = hp;
        }
        xn2s[half * 64 + px] = n2;
    }
    __syncthreads();

    // ---- resident A fragments: warp owns pixel rows 16*wid..+15 ----
    uint32_t Ah[4][4];
    {
        const int mtx = lane >> 3;
        const int r   = 16 * wid + (mtx & 1) * 8 + (lane & 7);
        const int kh  = (mtx >> 1) * 16;
        #pragma unroll
        for (int ks = 0; ks < 4; ks++) {
            int col = (ks * 32 + kh) ^ ((r & 7) * 16);
            ldsm_x4(Ah[ks][0], Ah[ks][1], Ah[ks][2], Ah[ks][3],
                    sb + OFF_A + r * 128 + col);
        }
    }

    // ---- sweep: 8 chunks x 4 j-pairs; 1-term fp16 MMA; FMNMX top-4 ----
    float a1 = 3.4e38f, a2 = 3.4e38f, a3 = 3.4e38f, a4 = 3.4e38f;  // row r
    float b1 = 3.4e38f, b2 = 3.4e38f, b3 = 3.4e38f, b4 = 3.4e38f;  // row r+8

    const int btile  = (lane >> 4) & 1;
    const int bkhalf = ((lane >> 3) & 1) * 16;
    const int brow   = lane & 7;

    for (int ch = 0; ch < NCHUNK; ch++) {
        if (ch + 1 < NCHUNK) {
            stage_B(sb + OFF_B + ((ch + 1) & 1) * 8192, ch + 1, tid);
            CP_COMMIT();
            CP_WAIT1();
        } else {
            CP_WAIT0();
        }
        __syncthreads();

        const uint32_t bbase = sb + OFF_B + (ch & 1) * 8192;
        #pragma unroll
        for (int jp = 0; jp < 4; jp++) {          // 16 codes per jp
            const int k0 = ch * CODES_PER_CHUNK + jp * 16 + 2 * (lane & 3);
            float e0, e1, f0, f1;
            asm("ld.shared.v2.f32 {%0,%1}, [%2];"
                : "=f"(e0), "=f"(e1) : "r"(sb + OFF_EN2 + k0 * 4));
            asm("ld.shared.v2.f32 {%0,%1}, [%2];"
                : "=f"(f0), "=f"(f1) : "r"(sb + OFF_EN2 + (k0 + 8) * 4));
            // accumulators pre-loaded with ||e||^2
            float c00 = e0, c01 = e1, c02 = e0, c03 = e1;   // tile 0
            float c10 = f0, c11 = f1, c12 = f0, c13 = f1;   // tile 1
            const int rr = jp * 16 + btile * 8 + brow;
            #pragma unroll
            for (int ks = 0; ks < 4; ks++) {
                int col = (ks * 32 + bkhalf) ^ ((rr & 7) * 16);
                uint32_t h0, h1, h2, h3;
                ldsm_x4(h0, h1, h2, h3, bbase + rr * 128 + col);
                mma_f16(c00, c01, c02, c03, Ah[ks][0], Ah[ks][1], Ah[ks][2], Ah[ks][3], h0, h1);
                mma_f16(c10, c11, c12, c13, Ah[ks][0], Ah[ks][1], Ah[ks][2], Ah[ks][3], h2, h3);
            }
            ins4(encd(c00, k0),     a1, a2, a3, a4);
            ins4(encd(c02, k0),     b1, b2, b3, b4);
            ins4(encd(c01, k0 + 1), a1, a2, a3, a4);
            ins4(encd(c03, k0 + 1), b1, b2, b3, b4);
            ins4(encd(c10, k0 + 8), a1, a2, a3, a4);
            ins4(encd(c12, k0 + 8), b1, b2, b3, b4);
            ins4(encd(c11, k0 + 9), a1, a2, a3, a4);
            ins4(encd(c13, k0 + 9), b1, b2, b3, b4);
        }
        __syncthreads();   // all warps done with buf[ch&1] before restage
    }

    // ---- merge quads across the 4 lanes sharing each accum row ----
    #pragma unroll
    for (int off = 1; off <= 2; off <<= 1) {
        float q1 = __shfl_xor_sync(0xffffffffu, a1, off);
        float q2 = __shfl_xor_sync(0xffffffffu, a2, off);
        float q3 = __shfl_xor_sync(0xffffffffu, a3, off);
        float q4 = __shfl_xor_sync(0xffffffffu, a4, off);
        ins4(q1, a1, a2, a3, a4); ins4(q2, a1, a2, a3, a4);
        ins4(q3, a1, a2, a3, a4); ins4(q4, a1, a2, a3, a4);
        q1 = __shfl_xor_sync(0xffffffffu, b1, off);
        q2 = __shfl_xor_sync(0xffffffffu, b2, off);
        q3 = __shfl_xor_sync(0xffffffffu, b3, off);
        q4 = __shfl_xor_sync(0xffffffffu, b4, off);
        ins4(q1, b1, b2, b3, b4); ins4(q2, b1, b2, b3, b4);
        ins4(q3, b1, b2, b3, b4); ins4(q4, b1, b2, b3, b4);
    }
    if ((lane & 3) == 0) {
        int r0 = 16 * wid + (lane >> 2);
        topv[r0 * 4 + 0] = a1; topv[r0 * 4 + 1] = a2;
        topv[r0 * 4 + 2] = a3; topv[r0 * 4 + 3] = a4;
        int r1 = r0 + 8;
        topv[r1 * 4 + 0] = b1; topv[r1 * 4 + 1] = b2;
        topv[r1 * 4 + 2] = b3; topv[r1 * 4 + 3] = b4;
    }
    __syncthreads();

    // ---- argmin resolution (threads 0..63, one pixel each) ----
    if (tid < 64) {
        const int p = p0 + tid;
        const float* xp = in + (p >> 12) * CHW + (p & (HWSZ - 1));
        float t1 = topv[tid * 4 + 0], t2 = topv[tid * 4 + 1];
        float t3 = topv[tid * 4 + 2], t4 = topv[tid * 4 + 3];
        int   j1 = decd(t1), j2 = decd(t2), j3 = decd(t3);

        const float xn2  = xn2s[tid] + xn2s[64 + tid];
        const float em2  = __int_as_float(g_emax_i);
        const float eps  = EPS_C * sqrtf(xn2 * em2) + EPS_M;

        int win;
        if (t2 - t1 >= eps) {
            win = j1;                          // certified
        } else if (t4 - t1 >= eps) {           // winner in {j1,j2,j3}
            float d1 = exact_dist(xp, emb, en2s[j1], j1);
            float d2 = exact_dist(xp, emb, en2s[j2], j2);
            float d3 = exact_dist(xp, emb, en2s[j3], j3);
            win = j1; float bd = d1;
            if (d2 < bd || (d2 == bd && j2 < win)) { bd = d2; win = j2; }
            if (d3 < bd || (d3 == bd && j3 < win)) { bd = d3; win = j3; }
        } else {
            win = -1;                          // rare: full exact scan
        }
        unsigned m = __ballot_sync(0xffffffffu, win < 0);
        while (m) {
            int src = __ffs(m) - 1; m &= m - 1;
            int pp = __shfl_sync(0xffffffffu, p, src);
            const float* xq = in + (pp >> 12) * CHW + (pp & (HWSZ - 1));
            float bd = 3.4e38f; int bi = 0;
            for (int kk = lane; kk < KCODES; kk += 32) {
                float dv = exact_dist(xq, emb, en2s[kk], kk);
                if (dv < bd || (dv == bd && kk < bi)) { bd = dv; bi = kk; }
            }
            #pragma unroll
            for (int o = 16; o; o >>= 1) {
                float od = __shfl_xor_sync(0xffffffffu, bd, o);
                int   oi = __shfl_xor_sync(0xffffffffu, bi, o);
                if (od < bd || (od == bd && oi < bi)) { bd = od; bi = oi; }
            }
            if (lane == src) win = bi;
        }

        winS[tid] = win;
        atomicAdd(&histS[win], 1);
        out[OUT_IDX_OFF + p] = (float)win;
    }
    __syncthreads();

    // ---- scatter + loss on all 128 threads (2 per pixel) ----
    float lossLocal = 0.0f;
    {
        const int px   = tid & 63;
        const int half = tid >> 6;
        const int p    = p0 + px;
        const int win  = winS[px];
        const float* xp = in  + (p >> 12) * CHW + (p & (HWSZ - 1)) + half * 32 * HWSZ;
        float*       op = out + (p >> 12) * CHW + (p & (HWSZ - 1)) + half * 32 * HWSZ;
        const float4* qr = (const float4*)(emb + (win << 6) + half * 32);
        #pragma unroll
        for (int c4 = 0; c4 < 8; c4++) {
            float4 q4 = qr[c4];
            float x0 = xp[(c4 * 4 + 0) * HWSZ];
            float x1 = xp[(c4 * 4 + 1) * HWSZ];
            float x2 = xp[(c4 * 4 + 2) * HWSZ];
            float x3 = xp[(c4 * 4 + 3) * HWSZ];
            op[(c4 * 4 + 0) * HWSZ] = q4.x;
            op[(c4 * 4 + 1) * HWSZ] = q4.y;
            op[(c4 * 4 + 2) * HWSZ] = q4.z;
            op[(c4 * 4 + 3) * HWSZ] = q4.w;
            float e0 = q4.x - x0, e1 = q4.y - x1, e2 = q4.z - x2, e3 = q4.w - x3;
            lossLocal += e0 * e0 + e1 * e1 + e2 * e2 + e3 * e3;
        }
    }
    #pragma unroll
    for (int o = 16; o; o >>= 1)
        lossLocal += __shfl_xor_sync(0xffffffffu, lossLocal, o);
    if (lane == 0) ((float*)(smc + OFF_WS))[wid] = lossLocal;
    __syncthreads();
    if (tid == 0) {
        float* ws = (float*)(smc + OFF_WS);
        g_part[blockIdx.x] = (ws[0] + ws[1]) + (ws[2] + ws[3]);
    }
    #pragma unroll
    for (int t = 0; t < 4; t++)
        atomicAdd(&g_hist[tid + t * THREADS], histS[tid + t * THREADS]);
}

// ---------------- final: scalars ----------------
extern "C" __global__ void vq_final(const float* __restrict__ w,
                                    float* __restrict__ out)
{
    __shared__ float red[KCODES];
    const int t = threadIdx.x;

    float pv = (float)g_hist[t] * (1.0f / (float)N_PIX);
    red[t] = pv * logf(pv + 1e-10f);
    __syncthreads();
    #pragma unroll
    for (int s = KCODES / 2; s > 0; s >>= 1) {
        if (t < s) red[t] += red[t + s];
        __syncthreads();
    }
    float perp = 0.0f;
    if (t == 0) perp = expf(-red[0]);
    __syncthreads();

    red[t] = (w[t] >= 0.01f) ? 1.0f : 0.0f;
    __syncthreads();
    #pragma unroll
    for (int s = KCODES / 2; s > 0; s >>= 1) {
        if (t < s) red[t] += red[t + s];
        __syncthreads();
    }
    float act = 0.0f;
    if (t == 0) act = red[0];
    __syncthreads();

    red[t] = g_part[t] + g_part[t + 512];   // NBLK = 1024
    __syncthreads();
    #pragma unroll
    for (int s = KCODES / 2; s > 0; s >>= 1) {
        if (t < s) red[t] += red[t + s];
        __syncthreads();
    }
    if (t == 0) {
        out[OUT_LOSS_OFF] = red[0] * (1.0f / ((float)N_PIX * (float)CDIM));
        out[OUT_PERP_OFF] = perp;
        out[OUT_ACT_OFF]  = act;
    }
}

extern "C" void kernel_launch(void* const* d_in, const int* in_sizes, int n_in,
                              void* d_out, int out_size)
{
    const float* in  = (const float*)d_in[0];
    const float* emb = (const float*)d_in[1];
    const float* w   = (const float*)d_in[2];
    float* out = (float*)d_out;

    cudaFuncSetAttribute(vq_main, cudaFuncAttributeMaxDynamicSharedMemorySize,
                         SMEM_MAIN);

    vq_prep<<<128, 256>>>(emb);
    vq_main<<<NBLK, THREADS, SMEM_MAIN>>>(in, emb, out);
    vq_final<<<1, KCODES>>>(w, out);
}